// round 13
// baseline (speedup 1.0000x reference)
#include <cuda_runtime.h>
#include <cuda_bf16.h>
#include <math.h>

// ---------------------------------------------------------------------------
// DTAN forward — bit-exact XLA:CPU (Eigen) emulation attempt.
//   convs/fc1: ascending-k single-accumulator FMA chains, k = (tap, ci) with
//              ci innermost; Eigen kc=256 depth panels combined left-to-right.
//   fc2/thetaB: naive mul+add (non-contracted), ascending.
//   exp: XLA:CPU inline Cephes (straight Horner, fma).  tanh: XLA fast-tanh.
//   scan: f32 non-contracted; interp f32; linspace i*f32(1/511), end=1.
// ---------------------------------------------------------------------------

#define NSAMP 1024
#define L0    512
#define C1    128
#define L1    252
#define C2    64
#define L2    81
#define C3    64
#define L3    39

// XLA:CPU GenerateVF32Exp (Cephes): valid bit-exact here; for |x|<=0.35 the
// Cody-Waite reduction is exactly zero (fx=0) and ldexp is identity.
__device__ __forceinline__ float cephes_expf(float x) {
    float fx = floorf(fmaf(x, 1.44269504088896341f, 0.5f));
    float r  = fmaf(fx, -0.693359375f, x);
    r        = fmaf(fx, 2.12194440e-4f, r);
    float z  = __fmul_rn(r, r);
    float y  = 1.9875691500E-4f;
    y = fmaf(y, r, 1.3981999507E-3f);
    y = fmaf(y, r, 8.3334519073E-3f);
    y = fmaf(y, r, 4.1665795894E-2f);
    y = fmaf(y, r, 1.6666665459E-1f);
    y = fmaf(y, r, 5.0000001201E-1f);
    y = fmaf(y, z, r);
    y = __fadd_rn(y, 1.0f);
    return ldexpf(y, (int)fx);
}

// XLA fast-tanh rational (fmuladd polynomial, clamp +-7.90531110763549805,
// passthrough |x| < 0.0004).
__device__ __forceinline__ float tanh_xla(float x) {
    float ax = fabsf(x);
    float xc = fminf(fmaxf(x, -7.90531110763549805f), 7.90531110763549805f);
    float x2 = __fmul_rn(xc, xc);
    float p = -2.76076847742355e-16f;
    p = fmaf(p, x2, 2.00018790482477e-13f);
    p = fmaf(p, x2, -8.60467152213735e-11f);
    p = fmaf(p, x2, 5.12229709037114e-08f);
    p = fmaf(p, x2, 1.48572235717979e-05f);
    p = fmaf(p, x2, 6.37261928875436e-04f);
    p = fmaf(p, x2, 4.89352455891786e-03f);
    float num = __fmul_rn(xc, p);
    float q = 1.19825839466702e-06f;
    q = fmaf(q, x2, 1.18534705686654e-04f);
    q = fmaf(q, x2, 2.26843463243900e-03f);
    q = fmaf(q, x2, 4.89352518554385e-03f);
    float r = __fdiv_rn(num, q);
    return (ax < 0.0004f) ? x : r;
}

// scratch
__device__ float g_buf1[(size_t)NSAMP * C1 * L1];   // conv1 out
__device__ float g_buf2[(size_t)NSAMP * C2 * L2];   // conv2 out
__device__ float g_ab[NSAMP * 12];                  // per-sample Ab
__device__ float g_w2t[128 * 9 * 64];               // w2 [ci][t][co]
__device__ float g_w3t[64 * 3 * 64];                // w3 [ci][t][co]

// ---------------------------------------------------------------------------
// k0: weight transposes into [ci][t][co]
// ---------------------------------------------------------------------------
__global__ void k0_transpose(const float* __restrict__ w2,
                             const float* __restrict__ w3) {
    int idx = blockIdx.x * 256 + threadIdx.x;
    if (idx < 128 * 9 * 64) {
        int co = idx & 63;
        int r  = idx >> 6;
        int t  = r % 9;
        int ci = r / 9;
        g_w2t[idx] = w2[(co * 128 + ci) * 9 + t];
    }
    if (idx < 64 * 3 * 64) {
        int co = idx & 63;
        int r  = idx >> 6;
        int t  = r % 3;
        int ci = r / 3;
        g_w3t[idx] = w3[(co * 64 + ci) * 3 + t];
    }
}

// ---------------------------------------------------------------------------
// k1: conv1 (K=7 single ascending fma chain) + pool(3,2) + bias + relu
// ---------------------------------------------------------------------------
__global__ __launch_bounds__(256) void k1_conv1(const float* __restrict__ x,
                                                const float* __restrict__ w1,
                                                const float* __restrict__ b1) {
    __shared__ float xs[L0];
    __shared__ float ts[128 * 32];
    int n   = blockIdx.x;
    int tid = threadIdx.x;

    for (int i = tid; i < L0; i += 256) xs[i] = x[(size_t)n * L0 + i];

    int c = tid >> 1, sub = tid & 1;
    float wr[7];
#pragma unroll
    for (int t = 0; t < 7; ++t) wr[t] = w1[c * 7 + t];
    float bc = b1[c];
    __syncthreads();

    for (int pt = 0; pt < 8; ++pt) {
        int p0 = pt * 32 + sub * 16;
        float cprev;
        {
            int j = 2 * p0;
            float s = 0.f;
#pragma unroll
            for (int t = 0; t < 7; ++t) s = fmaf(wr[t], xs[j + t], s);
            cprev = s;
        }
#pragma unroll
        for (int q = 0; q < 16; ++q) {
            int p = p0 + q;
            if (p < L1) {
                int j = 2 * p + 1;
                float c1 = 0.f, c2 = 0.f;
#pragma unroll
                for (int t = 0; t < 7; ++t) c1 = fmaf(wr[t], xs[j + t], c1);
#pragma unroll
                for (int t = 0; t < 7; ++t) c2 = fmaf(wr[t], xs[j + 1 + t], c2);
                float m = fmaxf(fmaxf(cprev, c1), c2);
                ts[c * 32 + sub * 16 + q] = fmaxf(__fadd_rn(m, bc), 0.f);
                cprev = c2;
            }
        }
        __syncthreads();
        for (int idx = tid; idx < 128 * 32; idx += 256) {
            int cc = idx >> 5, k = idx & 31, p = pt * 32 + k;
            if (p < L1)
                g_buf1[(size_t)n * (C1 * L1) + cc * L1 + p] = ts[idx];
        }
        __syncthreads();
    }
}

// ---------------------------------------------------------------------------
// k2: conv2, k-order (t outer, ci inner) ascending fma, Eigen kc=256 panels:
// [t0,t1][t2,t3][t4,t5][t6,t7][t8], panel chains from zero, combined by fadd
// left-to-right.  Then bias + pool(3,3) + relu.
// One block/sample; full 128x264 input strip in smem; weights via L1/L2 LDG.
// ---------------------------------------------------------------------------
#define K2_SMEM_BYTES (128 * 264 * 4)   // 135168

__global__ __launch_bounds__(256) void k2_conv2(const float* __restrict__ b2) {
    extern __shared__ float sm[];
    float* in_s = sm;   // 128 rows x 264 (252 valid + zero pad)

    int n   = blockIdx.x;
    int tid = threadIdx.x;
    int l   = tid & 31;
    int wg  = tid >> 5;
    int cobase = wg * 8;

    const float* inbase = g_buf1 + (size_t)n * (C1 * L1);
    for (int idx = tid; idx < 128 * 264; idx += 256) {
        int ci = idx / 264, j = idx - ci * 264;
        in_s[idx] = (j < L1) ? inbase[ci * L1 + j] : 0.f;
    }
    __syncthreads();

    float tot[64];
#pragma unroll
    for (int i = 0; i < 64; ++i) tot[i] = 0.f;

    for (int p = 0; p < 5; ++p) {
        float acc[64];
#pragma unroll
        for (int i = 0; i < 64; ++i) acc[i] = 0.f;

        int nt = (p < 4) ? 2 : 1;
        for (int tt = 0; tt < nt; ++tt) {
            int t = 2 * p + tt;
            const float* wt = g_w2t + t * 64 + cobase;
            for (int ci = 0; ci < 128; ++ci) {
                const float* xrow = in_s + ci * 264 + t + l;
                float xv[8];
#pragma unroll
                for (int u = 0; u < 8; ++u) xv[u] = xrow[u * 32];
                const float* wrow = wt + ci * 576;
#pragma unroll
                for (int coi = 0; coi < 8; ++coi) {
                    float wv = __ldg(wrow + coi);
#pragma unroll
                    for (int u = 0; u < 8; ++u)
                        acc[coi * 8 + u] = fmaf(wv, xv[u], acc[coi * 8 + u]);
                }
            }
        }
#pragma unroll
        for (int i = 0; i < 64; ++i) tot[i] = __fadd_rn(tot[i], acc[i]);
    }
    __syncthreads();

    float* conv_s = sm;  // 64 x 248
#pragma unroll
    for (int coi = 0; coi < 8; ++coi)
#pragma unroll
        for (int u = 0; u < 8; ++u) {
            int j = u * 32 + l;
            if (j < 244) conv_s[(cobase + coi) * 248 + j] = tot[coi * 8 + u];
        }
    __syncthreads();
    for (int idx = tid; idx < C2 * L2; idx += 256) {
        int co = idx / L2, i = idx - co * L2;
        const float* p3 = conv_s + co * 248 + 3 * i;
        float m = fmaxf(fmaxf(p3[0], p3[1]), p3[2]);
        g_buf2[(size_t)n * (C2 * L2) + idx] = fmaxf(__fadd_rn(m, b2[co]), 0.f);
    }
}

// ---------------------------------------------------------------------------
// k3: conv3 (K=192 single chain, t outer / ci inner) + pool + bias + relu,
// then fc1 (kc=256 panels, single ascending chains, 16 threads),
// fc2 (naive mul+add, tanh_xla), theta@B (naive mul+add).
// ---------------------------------------------------------------------------
#define K3_INSTRIDE 100
#define K3_SMEM_FLOATS (64 * K3_INSTRIDE + 64 * 3 * 64)   // 18688
#define K3_SMEM_BYTES  (K3_SMEM_FLOATS * 4)               // 74752

__global__ __launch_bounds__(256, 2) void k3_tail(const float* __restrict__ b3,
                                                  const float* __restrict__ fw1,
                                                  const float* __restrict__ fb1,
                                                  const float* __restrict__ fw2,
                                                  const float* __restrict__ fb2,
                                                  const float* __restrict__ Bb) {
    extern __shared__ float sm[];
    float* in_s = sm;           // 64 * 100
    float* w_s  = sm + 6400;    // 12288

    int n   = blockIdx.x;
    int tid = threadIdx.x;
    int l   = tid & 31;
    int wg  = tid >> 5;
    int cobase = wg * 8;

    const float* inb = g_buf2 + (size_t)n * (C2 * L2);
    for (int idx = tid; idx < 64 * K3_INSTRIDE; idx += 256) {
        int ci = idx / K3_INSTRIDE, j = idx - ci * K3_INSTRIDE;
        in_s[idx] = (j < L2) ? inb[ci * L2 + j] : 0.f;
    }
    for (int idx = tid; idx < 64 * 3 * 64; idx += 256) w_s[idx] = g_w3t[idx];
    __syncthreads();

    float acc[24];
#pragma unroll
    for (int i = 0; i < 24; ++i) acc[i] = 0.f;

    // single panel (K=192 <= 256): t outer, ci inner, ascending fma chain
    for (int t = 0; t < 3; ++t) {
        for (int ci = 0; ci < 64; ++ci) {
            const float* xrow = in_s + ci * K3_INSTRIDE + t + l;
            float xv[3];
#pragma unroll
            for (int u = 0; u < 3; ++u) xv[u] = xrow[u * 32];
            const float* wrow = w_s + ci * 192 + t * 64 + cobase;
#pragma unroll
            for (int coi = 0; coi < 8; ++coi) {
                float wv = wrow[coi];
#pragma unroll
                for (int u = 0; u < 3; ++u)
                    acc[coi * 3 + u] = fmaf(wv, xv[u], acc[coi * 3 + u]);
            }
        }
    }
    __syncthreads();

    float* conv_s = sm;  // 64 * 80
#pragma unroll
    for (int coi = 0; coi < 8; ++coi)
#pragma unroll
        for (int u = 0; u < 3; ++u) {
            int j = u * 32 + l;
            if (j < 80) conv_s[(cobase + coi) * 80 + j] = acc[coi * 3 + u];
        }
    __syncthreads();

    float* xs_s = sm + 6400;
    for (int idx = tid; idx < C3 * L3; idx += 256) {
        int co = idx / L3, i = idx - co * L3;
        const float* p3 = conv_s + co * 80 + 2 * i;
        float m = fmaxf(fmaxf(p3[0], p3[1]), p3[2]);
        xs_s[idx] = fmaxf(__fadd_rn(m, b3[co]), 0.f);   // idx == co*39+i
    }
    __syncthreads();

    float* h_s  = xs_s + 2496;
    float* th_s = h_s + 16;

    // fc1: single ascending chain per output with kc=256 panels
    if (tid < 16) {
        const float* wrow = fw1 + tid * 2496;
        float tot = 0.f;
        int e = 0;
        for (int panel = 0; panel < 10; ++panel) {
            int len = (panel < 9) ? 256 : 192;
            float a = 0.f;
            for (int q = 0; q < len; ++q) {
                a = fmaf(xs_s[e], __ldg(wrow + e), a);
                ++e;
            }
            tot = __fadd_rn(tot, a);
        }
        h_s[tid] = fmaxf(__fadd_rn(tot, fb1[tid]), 0.f);
    }
    __syncthreads();

    // fc2: naive mul+add ascending, then +bias, tanh
    if (tid < 5) {
        float z = 0.f;
#pragma unroll
        for (int m = 0; m < 16; ++m)
            z = __fadd_rn(z, __fmul_rn(h_s[m], fw2[tid * 16 + m]));
        z = __fadd_rn(z, fb2[tid]);
        th_s[tid] = tanh_xla(z);
    }
    __syncthreads();

    // theta @ B^T: naive mul+add ascending
    if (tid < 12) {
        float ab = 0.f;
#pragma unroll
        for (int m = 0; m < 5; ++m)
            ab = __fadd_rn(ab, __fmul_rn(th_s[m], Bb[tid * 5 + m]));
        g_ab[n * 12 + tid] = ab;
    }
}

// ---------------------------------------------------------------------------
// k4: CPAB integration, f32 non-contracted, hoisted per-cell constants
// (bitwise equal to per-step recomputation), Cephes exp; f32 interpolation.
// ---------------------------------------------------------------------------
__global__ __launch_bounds__(512) void k4_warp_interp(const float* __restrict__ xd,
                                                      float* __restrict__ out) {
    __shared__ float xs[L0];
    __shared__ float e_s[6], s_s[6];
    int n   = blockIdx.x;
    int tid = threadIdx.x;

    xs[tid] = xd[(size_t)n * L0 + tid];
    if (tid < 6) {
        float a = g_ab[n * 12 + 2 * tid];
        float b = g_ab[n * 12 + 2 * tid + 1];
        const float dtf = 0.02f;
        if (fabsf(a) < 1e-6f) {
            e_s[tid] = 1.0f;                         // e*x + s == x + b*dt
            s_s[tid] = __fmul_rn(b, dtf);
        } else {
            float arg = __fmul_rn(a, dtf);
            float e   = cephes_expf(arg);            // XLA:CPU inline exp
            e_s[tid] = e;
            float t2 = __fdiv_rn(b, a);
            float t3 = __fsub_rn(e, 1.0f);
            s_s[tid] = __fmul_rn(t2, t3);
        }
    }
    __syncthreads();

    const float stepf = 1.0f / 511.0f;
    float x = (tid == 511) ? 1.0f : __fmul_rn((float)tid, stepf);

#pragma unroll 1
    for (int s = 0; s < 50; ++s) {
        int c = (int)__fmul_rn(x, 6.0f);
        c = min(max(c, 0), 5);
        float xn = __fadd_rn(__fmul_rn(e_s[c], x), s_s[c]);  // no FMA contract
        x = fminf(fmaxf(xn, 0.0f), 1.0f);
    }

    float pos = __fmul_rn(x, 511.0f);
    int i0 = (int)floorf(pos);
    i0 = min(max(i0, 0), 510);
    float w  = __fsub_rn(pos, (float)i0);
    float g0 = xs[i0];
    float g1 = xs[i0 + 1];
    out[(size_t)n * L0 + tid] =
        __fadd_rn(__fmul_rn(g0, __fsub_rn(1.0f, w)), __fmul_rn(g1, w));
}

// ---------------------------------------------------------------------------
extern "C" void kernel_launch(void* const* d_in, const int* in_sizes, int n_in,
                              void* d_out, int out_size) {
    const float* x   = (const float*)d_in[0];
    const float* w1  = (const float*)d_in[1];
    const float* b1  = (const float*)d_in[2];
    const float* w2  = (const float*)d_in[3];
    const float* b2  = (const float*)d_in[4];
    const float* w3  = (const float*)d_in[5];
    const float* b3  = (const float*)d_in[6];
    const float* fw1 = (const float*)d_in[7];
    const float* fb1 = (const float*)d_in[8];
    const float* fw2 = (const float*)d_in[9];
    const float* fb2 = (const float*)d_in[10];
    const float* Bb  = (const float*)d_in[11];

    cudaFuncSetAttribute(k2_conv2, cudaFuncAttributeMaxDynamicSharedMemorySize,
                         K2_SMEM_BYTES);
    cudaFuncSetAttribute(k3_tail, cudaFuncAttributeMaxDynamicSharedMemorySize,
                         K3_SMEM_BYTES);

    k0_transpose<<<(128 * 9 * 64 + 255) / 256, 256>>>(w2, w3);
    k1_conv1<<<NSAMP, 256>>>(x, w1, b1);
    k2_conv2<<<NSAMP, 256, K2_SMEM_BYTES>>>(b2);
    k3_tail<<<NSAMP, 256, K3_SMEM_BYTES>>>(b3, fw1, fb1, fw2, fb2, Bb);
    k4_warp_interp<<<NSAMP, 512>>>(x, (float*)d_out);
}

// round 14
// speedup vs baseline: 2.2125x; 2.2125x over previous
#include <cuda_runtime.h>
#include <cuda_bf16.h>
#include <math.h>

// ---------------------------------------------------------------------------
// DTAN forward — bit-exact XLA:CPU (Eigen) emulation (PASSED R13 @ 8.205e-4).
// R14: performance only. All FP chains bitwise identical to R13:
//   - k2 uses fma.rn.f32x2 (each lane an independent IEEE-rn FMA) pairing
//     adjacent co; per-accumulator order (panel -> t -> ci) unchanged;
//     panel combine via add.rn.f32x2 (lane-wise __fadd_rn).
//   - k2 stages per-t weights in smem (same values, same order).
//   - k3 fc1: 10 independent kc=256 panel chains computed in parallel from a
//     transposed fw1 [e][o]; combined left-to-right exactly as before.
// ---------------------------------------------------------------------------

#define NSAMP 1024
#define L0    512
#define C1    128
#define L1    252
#define C2    64
#define L2    81
#define C3    64
#define L3    39

typedef unsigned long long u64;

#define PACK2(d, lo, hi)  asm("mov.b64 %0, {%1, %2};" : "=l"(d) : "f"(lo), "f"(hi))
#define UNPACK2(lo, hi, s) asm("mov.b64 {%0, %1}, %2;" : "=f"(lo), "=f"(hi) : "l"(s))
#define FMA2(d, a, b)     asm("fma.rn.f32x2 %0, %1, %2, %3;" : "=l"(d) : "l"(a), "l"(b), "l"(d))
#define ADD2(d, a, b)     asm("add.rn.f32x2 %0, %1, %2;" : "=l"(d) : "l"(a), "l"(b))

// XLA:CPU GenerateVF32Exp (Cephes) — bit-exact for this argument range.
__device__ __forceinline__ float cephes_expf(float x) {
    float fx = floorf(fmaf(x, 1.44269504088896341f, 0.5f));
    float r  = fmaf(fx, -0.693359375f, x);
    r        = fmaf(fx, 2.12194440e-4f, r);
    float z  = __fmul_rn(r, r);
    float y  = 1.9875691500E-4f;
    y = fmaf(y, r, 1.3981999507E-3f);
    y = fmaf(y, r, 8.3334519073E-3f);
    y = fmaf(y, r, 4.1665795894E-2f);
    y = fmaf(y, r, 1.6666665459E-1f);
    y = fmaf(y, r, 5.0000001201E-1f);
    y = fmaf(y, z, r);
    y = __fadd_rn(y, 1.0f);
    return ldexpf(y, (int)fx);
}

// XLA fast-tanh rational.
__device__ __forceinline__ float tanh_xla(float x) {
    float ax = fabsf(x);
    float xc = fminf(fmaxf(x, -7.90531110763549805f), 7.90531110763549805f);
    float x2 = __fmul_rn(xc, xc);
    float p = -2.76076847742355e-16f;
    p = fmaf(p, x2, 2.00018790482477e-13f);
    p = fmaf(p, x2, -8.60467152213735e-11f);
    p = fmaf(p, x2, 5.12229709037114e-08f);
    p = fmaf(p, x2, 1.48572235717979e-05f);
    p = fmaf(p, x2, 6.37261928875436e-04f);
    p = fmaf(p, x2, 4.89352455891786e-03f);
    float num = __fmul_rn(xc, p);
    float q = 1.19825839466702e-06f;
    q = fmaf(q, x2, 1.18534705686654e-04f);
    q = fmaf(q, x2, 2.26843463243900e-03f);
    q = fmaf(q, x2, 4.89352518554385e-03f);
    float r = __fdiv_rn(num, q);
    return (ax < 0.0004f) ? x : r;
}

// scratch
__device__ float g_buf1[(size_t)NSAMP * C1 * L1];
__device__ float g_buf2[(size_t)NSAMP * C2 * L2];
__device__ float g_ab[NSAMP * 12];
__device__ float g_w2t[128 * 9 * 64];    // [ci][t][co]
__device__ float g_w3t[64 * 3 * 64];     // [ci][t][co]
__device__ float g_fw1t[2496 * 16];      // [e][o]

// ---------------------------------------------------------------------------
// k0: weight transposes
// ---------------------------------------------------------------------------
__global__ void k0_transpose(const float* __restrict__ w2,
                             const float* __restrict__ w3,
                             const float* __restrict__ fw1) {
    int idx = blockIdx.x * 256 + threadIdx.x;
    if (idx < 128 * 9 * 64) {
        int co = idx & 63;
        int r  = idx >> 6;
        int t  = r % 9;
        int ci = r / 9;
        g_w2t[idx] = w2[(co * 128 + ci) * 9 + t];
    }
    if (idx < 64 * 3 * 64) {
        int co = idx & 63;
        int r  = idx >> 6;
        int t  = r % 3;
        int ci = r / 3;
        g_w3t[idx] = w3[(co * 64 + ci) * 3 + t];
    }
    if (idx < 2496 * 16) {
        int o = idx & 15;
        int e = idx >> 4;
        g_fw1t[idx] = fw1[o * 2496 + e];
    }
}

// ---------------------------------------------------------------------------
// k1: conv1 (K=7 ascending fma chain) + pool(3,2) + bias + relu  (unchanged)
// ---------------------------------------------------------------------------
__global__ __launch_bounds__(256) void k1_conv1(const float* __restrict__ x,
                                                const float* __restrict__ w1,
                                                const float* __restrict__ b1) {
    __shared__ float xs[L0];
    __shared__ float ts[128 * 32];
    int n   = blockIdx.x;
    int tid = threadIdx.x;

    for (int i = tid; i < L0; i += 256) xs[i] = x[(size_t)n * L0 + i];

    int c = tid >> 1, sub = tid & 1;
    float wr[7];
#pragma unroll
    for (int t = 0; t < 7; ++t) wr[t] = w1[c * 7 + t];
    float bc = b1[c];
    __syncthreads();

    for (int pt = 0; pt < 8; ++pt) {
        int p0 = pt * 32 + sub * 16;
        float cprev;
        {
            int j = 2 * p0;
            float s = 0.f;
#pragma unroll
            for (int t = 0; t < 7; ++t) s = fmaf(wr[t], xs[j + t], s);
            cprev = s;
        }
#pragma unroll
        for (int q = 0; q < 16; ++q) {
            int p = p0 + q;
            if (p < L1) {
                int j = 2 * p + 1;
                float c1 = 0.f, c2 = 0.f;
#pragma unroll
                for (int t = 0; t < 7; ++t) c1 = fmaf(wr[t], xs[j + t], c1);
#pragma unroll
                for (int t = 0; t < 7; ++t) c2 = fmaf(wr[t], xs[j + 1 + t], c2);
                float m = fmaxf(fmaxf(cprev, c1), c2);
                ts[c * 32 + sub * 16 + q] = fmaxf(__fadd_rn(m, bc), 0.f);
                cprev = c2;
            }
        }
        __syncthreads();
        for (int idx = tid; idx < 128 * 32; idx += 256) {
            int cc = idx >> 5, k = idx & 31, p = pt * 32 + k;
            if (p < L1)
                g_buf1[(size_t)n * (C1 * L1) + cc * L1 + p] = ts[idx];
        }
        __syncthreads();
    }
}

// ---------------------------------------------------------------------------
// k2: conv2, Eigen kc=256 panels [t0,t1][t2,t3][t4,t5][t6,t7][t8],
// (t outer, ci inner) ascending fma chains — now packed as f32x2 over
// adjacent co pairs (bitwise-identical lanes), weights staged per t in smem.
// ---------------------------------------------------------------------------
#define K2_SMEM_BYTES ((128 * 264 + 128 * 64) * 4)   // 135168 + 32768 = 167936

__global__ __launch_bounds__(256) void k2_conv2(const float* __restrict__ b2) {
    extern __shared__ float sm[];
    float* in_s = sm;                 // 128 x 264 (252 valid + zero pad)
    float* w_s  = sm + 128 * 264;     // 128 x 64 (weights for current t)

    int n   = blockIdx.x;
    int tid = threadIdx.x;
    int l   = tid & 31;
    int wg  = tid >> 5;
    int cobase = wg * 8;

    const float* inbase = g_buf1 + (size_t)n * (C1 * L1);
    for (int idx = tid; idx < 128 * 264; idx += 256) {
        int ci = idx / 264, j = idx - ci * 264;
        in_s[idx] = (j < L1) ? inbase[ci * L1 + j] : 0.f;
    }

    u64 tot2[32];
#pragma unroll
    for (int i = 0; i < 32; ++i) tot2[i] = 0ull;   // (0.f, 0.f)

    for (int p = 0; p < 5; ++p) {
        u64 acc2[32];
#pragma unroll
        for (int i = 0; i < 32; ++i) acc2[i] = 0ull;

        int nt = (p < 4) ? 2 : 1;
        for (int tt = 0; tt < nt; ++tt) {
            int t = 2 * p + tt;
            __syncthreads();   // all readers done with previous w_s contents
            for (int i = tid; i < 128 * 64; i += 256) {
                int ci = i >> 6, co = i & 63;
                w_s[i] = g_w2t[ci * 576 + t * 64 + co];
            }
            __syncthreads();

            for (int ci = 0; ci < 128; ++ci) {
                const float* xrow = in_s + ci * 264 + t + l;
                u64 xd[8];
#pragma unroll
                for (int u = 0; u < 8; ++u) {
                    float xv = xrow[u * 32];
                    PACK2(xd[u], xv, xv);
                }
                const u64* wp = (const u64*)(w_s + ci * 64 + cobase);
                u64 w0 = wp[0], w1 = wp[1], w2 = wp[2], w3 = wp[3];
#pragma unroll
                for (int u = 0; u < 8; ++u) FMA2(acc2[0 * 8 + u], xd[u], w0);
#pragma unroll
                for (int u = 0; u < 8; ++u) FMA2(acc2[1 * 8 + u], xd[u], w1);
#pragma unroll
                for (int u = 0; u < 8; ++u) FMA2(acc2[2 * 8 + u], xd[u], w2);
#pragma unroll
                for (int u = 0; u < 8; ++u) FMA2(acc2[3 * 8 + u], xd[u], w3);
            }
        }
#pragma unroll
        for (int i = 0; i < 32; ++i) ADD2(tot2[i], tot2[i], acc2[i]);
    }
    __syncthreads();

    float* conv_s = sm;  // 64 x 248
#pragma unroll
    for (int cp = 0; cp < 4; ++cp)
#pragma unroll
        for (int u = 0; u < 8; ++u) {
            float lo, hi;
            UNPACK2(lo, hi, tot2[cp * 8 + u]);
            int j = u * 32 + l;
            if (j < 244) {
                conv_s[(cobase + 2 * cp + 0) * 248 + j] = lo;
                conv_s[(cobase + 2 * cp + 1) * 248 + j] = hi;
            }
        }
    __syncthreads();
    for (int idx = tid; idx < C2 * L2; idx += 256) {
        int co = idx / L2, i = idx - co * L2;
        const float* p3 = conv_s + co * 248 + 3 * i;
        float m = fmaxf(fmaxf(p3[0], p3[1]), p3[2]);
        g_buf2[(size_t)n * (C2 * L2) + idx] = fmaxf(__fadd_rn(m, b2[co]), 0.f);
    }
}

// ---------------------------------------------------------------------------
// k3: conv3 (K=192 single chain, t outer / ci inner) + pool + bias + relu,
// fc1: 10 independent kc=256 panel chains on 160 threads (transposed fw1),
// combined left-to-right; fc2 naive mul+add + tanh_xla; theta@B naive.
// ---------------------------------------------------------------------------
#define K3_INSTRIDE 100
#define K3_SMEM_FLOATS (64 * K3_INSTRIDE + 64 * 3 * 64)   // 18688
#define K3_SMEM_BYTES  (K3_SMEM_FLOATS * 4)               // 74752

__global__ __launch_bounds__(256, 2) void k3_tail(const float* __restrict__ b3,
                                                  const float* __restrict__ fb1,
                                                  const float* __restrict__ fw2,
                                                  const float* __restrict__ fb2,
                                                  const float* __restrict__ Bb) {
    extern __shared__ float sm[];
    float* in_s = sm;           // 64 * 100
    float* w_s  = sm + 6400;    // 12288

    int n   = blockIdx.x;
    int tid = threadIdx.x;
    int l   = tid & 31;
    int wg  = tid >> 5;
    int cobase = wg * 8;

    const float* inb = g_buf2 + (size_t)n * (C2 * L2);
    for (int idx = tid; idx < 64 * K3_INSTRIDE; idx += 256) {
        int ci = idx / K3_INSTRIDE, j = idx - ci * K3_INSTRIDE;
        in_s[idx] = (j < L2) ? inb[ci * L2 + j] : 0.f;
    }
    for (int idx = tid; idx < 64 * 3 * 64; idx += 256) w_s[idx] = g_w3t[idx];
    __syncthreads();

    float acc[24];
#pragma unroll
    for (int i = 0; i < 24; ++i) acc[i] = 0.f;

    for (int t = 0; t < 3; ++t) {
        for (int ci = 0; ci < 64; ++ci) {
            const float* xrow = in_s + ci * K3_INSTRIDE + t + l;
            float xv[3];
#pragma unroll
            for (int u = 0; u < 3; ++u) xv[u] = xrow[u * 32];
            const float* wrow = w_s + ci * 192 + t * 64 + cobase;
#pragma unroll
            for (int coi = 0; coi < 8; ++coi) {
                float wv = wrow[coi];
#pragma unroll
                for (int u = 0; u < 3; ++u)
                    acc[coi * 3 + u] = fmaf(wv, xv[u], acc[coi * 3 + u]);
            }
        }
    }
    __syncthreads();

    float* conv_s = sm;  // 64 * 80
#pragma unroll
    for (int coi = 0; coi < 8; ++coi)
#pragma unroll
        for (int u = 0; u < 3; ++u) {
            int j = u * 32 + l;
            if (j < 80) conv_s[(cobase + coi) * 80 + j] = acc[coi * 3 + u];
        }
    __syncthreads();

    float* xs_s = sm + 6400;
    for (int idx = tid; idx < C3 * L3; idx += 256) {
        int co = idx / L3, i = idx - co * L3;
        const float* p3 = conv_s + co * 80 + 2 * i;
        float m = fmaxf(fmaxf(p3[0], p3[1]), p3[2]);
        xs_s[idx] = fmaxf(__fadd_rn(m, b3[co]), 0.f);
    }
    __syncthreads();

    float* pan_s = xs_s + 2496;   // 160
    float* h_s   = pan_s + 160;   // 16
    float* th_s  = h_s + 16;      // 5

    // fc1 panel chains: thread = p*16 + o ; each chain identical to R13's.
    if (tid < 160) {
        int o = tid & 15;
        int p = tid >> 4;
        int e0  = p * 256;
        int len = (p < 9) ? 256 : 192;
        float a = 0.f;
        const float* wt = g_fw1t + e0 * 16 + o;
#pragma unroll 8
        for (int q = 0; q < len; ++q)
            a = fmaf(xs_s[e0 + q], __ldg(wt + q * 16), a);
        pan_s[p * 16 + o] = a;
    }
    __syncthreads();

    if (tid < 16) {
        float tot = 0.f;
#pragma unroll
        for (int p = 0; p < 10; ++p)
            tot = __fadd_rn(tot, pan_s[p * 16 + tid]);
        h_s[tid] = fmaxf(__fadd_rn(tot, fb1[tid]), 0.f);
    }
    __syncthreads();

    if (tid < 5) {
        float z = 0.f;
#pragma unroll
        for (int m = 0; m < 16; ++m)
            z = __fadd_rn(z, __fmul_rn(h_s[m], fw2[tid * 16 + m]));
        z = __fadd_rn(z, fb2[tid]);
        th_s[tid] = tanh_xla(z);
    }
    __syncthreads();

    if (tid < 12) {
        float ab = 0.f;
#pragma unroll
        for (int m = 0; m < 5; ++m)
            ab = __fadd_rn(ab, __fmul_rn(th_s[m], Bb[tid * 5 + m]));
        g_ab[n * 12 + tid] = ab;
    }
}

// ---------------------------------------------------------------------------
// k4: CPAB integration (unchanged from R13 — bit-exact path)
// ---------------------------------------------------------------------------
__global__ __launch_bounds__(512) void k4_warp_interp(const float* __restrict__ xd,
                                                      float* __restrict__ out) {
    __shared__ float xs[L0];
    __shared__ float e_s[6], s_s[6];
    int n   = blockIdx.x;
    int tid = threadIdx.x;

    xs[tid] = xd[(size_t)n * L0 + tid];
    if (tid < 6) {
        float a = g_ab[n * 12 + 2 * tid];
        float b = g_ab[n * 12 + 2 * tid + 1];
        const float dtf = 0.02f;
        if (fabsf(a) < 1e-6f) {
            e_s[tid] = 1.0f;
            s_s[tid] = __fmul_rn(b, dtf);
        } else {
            float arg = __fmul_rn(a, dtf);
            float e   = cephes_expf(arg);
            e_s[tid] = e;
            float t2 = __fdiv_rn(b, a);
            float t3 = __fsub_rn(e, 1.0f);
            s_s[tid] = __fmul_rn(t2, t3);
        }
    }
    __syncthreads();

    const float stepf = 1.0f / 511.0f;
    float x = (tid == 511) ? 1.0f : __fmul_rn((float)tid, stepf);

#pragma unroll 1
    for (int s = 0; s < 50; ++s) {
        int c = (int)__fmul_rn(x, 6.0f);
        c = min(max(c, 0), 5);
        float xn = __fadd_rn(__fmul_rn(e_s[c], x), s_s[c]);
        x = fminf(fmaxf(xn, 0.0f), 1.0f);
    }

    float pos = __fmul_rn(x, 511.0f);
    int i0 = (int)floorf(pos);
    i0 = min(max(i0, 0), 510);
    float w  = __fsub_rn(pos, (float)i0);
    float g0 = xs[i0];
    float g1 = xs[i0 + 1];
    out[(size_t)n * L0 + tid] =
        __fadd_rn(__fmul_rn(g0, __fsub_rn(1.0f, w)), __fmul_rn(g1, w));
}

// ---------------------------------------------------------------------------
extern "C" void kernel_launch(void* const* d_in, const int* in_sizes, int n_in,
                              void* d_out, int out_size) {
    const float* x   = (const float*)d_in[0];
    const float* w1  = (const float*)d_in[1];
    const float* b1  = (const float*)d_in[2];
    const float* w2  = (const float*)d_in[3];
    const float* b2  = (const float*)d_in[4];
    const float* w3  = (const float*)d_in[5];
    const float* b3  = (const float*)d_in[6];
    const float* fw1 = (const float*)d_in[7];
    const float* fb1 = (const float*)d_in[8];
    const float* fw2 = (const float*)d_in[9];
    const float* fb2 = (const float*)d_in[10];
    const float* Bb  = (const float*)d_in[11];

    cudaFuncSetAttribute(k2_conv2, cudaFuncAttributeMaxDynamicSharedMemorySize,
                         K2_SMEM_BYTES);
    cudaFuncSetAttribute(k3_tail, cudaFuncAttributeMaxDynamicSharedMemorySize,
                         K3_SMEM_BYTES);

    k0_transpose<<<(2496 * 16 + 255) / 256 > 288 ? (2496 * 16 + 255) / 256 : 288,
                  256>>>(w2, w3, fw1);
    k1_conv1<<<NSAMP, 256>>>(x, w1, b1);
    k2_conv2<<<NSAMP, 256, K2_SMEM_BYTES>>>(b2);
    k3_tail<<<NSAMP, 256, K3_SMEM_BYTES>>>(b3, fb1, fw2, fb2, Bb);
    k4_warp_interp<<<NSAMP, 512>>>(x, (float*)d_out);
}

// round 16
// speedup vs baseline: 3.0683x; 1.3868x over previous
#include <cuda_runtime.h>
#include <cuda_bf16.h>
#include <math.h>

// ---------------------------------------------------------------------------
// DTAN forward — bit-exact XLA:CPU (Eigen) emulation (PASS @ rel_err 8.205e-4).
// R16 = R15 with the k0 launch-size regression fixed (288 blocks covers all
// 73728 g_w2t entries; R15 launched 156 and left g_w2t half-poisoned).
// All FP chains bitwise identical to R13/R14:
//   - conv1 fused into k2 (identical fmaf chains, no HBM round trip)
//   - k2: f32x2 co-pair packing, per-panel weight staging in smem
//   - k3: conv3 f32x2 co-pair packing + LDS.128 weights
// ---------------------------------------------------------------------------

#define NSAMP 1024
#define L0    512
#define C1    128
#define L1    252
#define C2    64
#define L2    81
#define C3    64
#define L3    39

typedef unsigned long long u64;

#define PACK2(d, lo, hi)  asm("mov.b64 %0, {%1, %2};" : "=l"(d) : "f"(lo), "f"(hi))
#define UNPACK2(lo, hi, s) asm("mov.b64 {%0, %1}, %2;" : "=f"(lo), "=f"(hi) : "l"(s))
#define FMA2(d, a, b)     asm("fma.rn.f32x2 %0, %1, %2, %3;" : "=l"(d) : "l"(a), "l"(b), "l"(d))
#define ADD2(d, a, b)     asm("add.rn.f32x2 %0, %1, %2;" : "=l"(d) : "l"(a), "l"(b))

// XLA:CPU GenerateVF32Exp (Cephes) — bit-exact in this argument range.
__device__ __forceinline__ float cephes_expf(float x) {
    float fx = floorf(fmaf(x, 1.44269504088896341f, 0.5f));
    float r  = fmaf(fx, -0.693359375f, x);
    r        = fmaf(fx, 2.12194440e-4f, r);
    float z  = __fmul_rn(r, r);
    float y  = 1.9875691500E-4f;
    y = fmaf(y, r, 1.3981999507E-3f);
    y = fmaf(y, r, 8.3334519073E-3f);
    y = fmaf(y, r, 4.1665795894E-2f);
    y = fmaf(y, r, 1.6666665459E-1f);
    y = fmaf(y, r, 5.0000001201E-1f);
    y = fmaf(y, z, r);
    y = __fadd_rn(y, 1.0f);
    return ldexpf(y, (int)fx);
}

// XLA fast-tanh rational.
__device__ __forceinline__ float tanh_xla(float x) {
    float ax = fabsf(x);
    float xc = fminf(fmaxf(x, -7.90531110763549805f), 7.90531110763549805f);
    float x2 = __fmul_rn(xc, xc);
    float p = -2.76076847742355e-16f;
    p = fmaf(p, x2, 2.00018790482477e-13f);
    p = fmaf(p, x2, -8.60467152213735e-11f);
    p = fmaf(p, x2, 5.12229709037114e-08f);
    p = fmaf(p, x2, 1.48572235717979e-05f);
    p = fmaf(p, x2, 6.37261928875436e-04f);
    p = fmaf(p, x2, 4.89352455891786e-03f);
    float num = __fmul_rn(xc, p);
    float q = 1.19825839466702e-06f;
    q = fmaf(q, x2, 1.18534705686654e-04f);
    q = fmaf(q, x2, 2.26843463243900e-03f);
    q = fmaf(q, x2, 4.89352518554385e-03f);
    float r = __fdiv_rn(num, q);
    return (ax < 0.0004f) ? x : r;
}

// scratch
__device__ float g_buf2[(size_t)NSAMP * C2 * L2];
__device__ float g_ab[NSAMP * 12];
__device__ float g_w2t[128 * 9 * 64];    // [ci][t][co]
__device__ float g_w3t[64 * 3 * 64];     // [ci][t][co]
__device__ float g_fw1t[2496 * 16];      // [e][o]

// ---------------------------------------------------------------------------
// k0: weight transposes (needs >= 288 blocks of 256: g_w2t has 73728 entries)
// ---------------------------------------------------------------------------
__global__ void k0_transpose(const float* __restrict__ w2,
                             const float* __restrict__ w3,
                             const float* __restrict__ fw1) {
    int idx = blockIdx.x * 256 + threadIdx.x;
    if (idx < 128 * 9 * 64) {
        int co = idx & 63;
        int r  = idx >> 6;
        int t  = r % 9;
        int ci = r / 9;
        g_w2t[idx] = w2[(co * 128 + ci) * 9 + t];
    }
    if (idx < 64 * 3 * 64) {
        int co = idx & 63;
        int r  = idx >> 6;
        int t  = r % 3;
        int ci = r / 3;
        g_w3t[idx] = w3[(co * 64 + ci) * 3 + t];
    }
    if (idx < 2496 * 16) {
        int o = idx & 15;
        int e = idx >> 4;
        g_fw1t[idx] = fw1[o * 2496 + e];
    }
}

// ---------------------------------------------------------------------------
// k2: FUSED conv1(+pool+relu) -> conv2 (Eigen kc=256 panels, f32x2 packed)
//     -> bias + pool(3,3) + relu -> g_buf2.
// smem: in_s[128][264] + w_s[2][128][64] + xs[512]
// ---------------------------------------------------------------------------
#define K2_SMEM_FLOATS (128 * 264 + 2 * 128 * 64 + 512)
#define K2_SMEM_BYTES  (K2_SMEM_FLOATS * 4)   // 202752

__global__ __launch_bounds__(256) void k2_fused(const float* __restrict__ x,
                                                const float* __restrict__ w1,
                                                const float* __restrict__ b1,
                                                const float* __restrict__ b2) {
    extern __shared__ float sm[];
    float* in_s = sm;                       // 128 x 264
    float* w_s  = sm + 128 * 264;           // 2 x 128 x 64
    float* xs   = w_s + 2 * 128 * 64;       // 512

    int n   = blockIdx.x;
    int tid = threadIdx.x;
    int l   = tid & 31;
    int wg  = tid >> 5;
    int cobase = wg * 8;

    // ---- conv1 phase (bitwise identical chains to the original k1) ----
    for (int i = tid; i < L0; i += 256) xs[i] = x[(size_t)n * L0 + i];

    {
        int c = tid >> 1, sub = tid & 1;
        float wr[7];
#pragma unroll
        for (int t = 0; t < 7; ++t) wr[t] = w1[c * 7 + t];
        float bc = b1[c];
        // zero-pad columns 252..263
        if (sub == 0) {
#pragma unroll
            for (int jj = L1; jj < 264; ++jj) in_s[c * 264 + jj] = 0.f;
        }
        __syncthreads();

        int j0 = sub * 126;
        float cprev;
        {
            int j = 2 * j0;
            float s = 0.f;
#pragma unroll
            for (int t = 0; t < 7; ++t) s = fmaf(wr[t], xs[j + t], s);
            cprev = s;
        }
        for (int q = 0; q < 126; ++q) {
            int p = j0 + q;
            int j = 2 * p + 1;
            float c1 = 0.f, c2 = 0.f;
#pragma unroll
            for (int t = 0; t < 7; ++t) c1 = fmaf(wr[t], xs[j + t], c1);
#pragma unroll
            for (int t = 0; t < 7; ++t) c2 = fmaf(wr[t], xs[j + 1 + t], c2);
            float m = fmaxf(fmaxf(cprev, c1), c2);
            in_s[c * 264 + p] = fmaxf(__fadd_rn(m, bc), 0.f);
            cprev = c2;
        }
    }

    // ---- conv2: 5 Eigen panels [t0,t1][t2,t3][t4,t5][t6,t7][t8] ----
    u64 tot2[32];
#pragma unroll
    for (int i = 0; i < 32; ++i) tot2[i] = 0ull;

    for (int p = 0; p < 5; ++p) {
        int nt = (p < 4) ? 2 : 1;

        __syncthreads();   // prior w_s readers done (first time: in_s ready)
        for (int i = tid; i < nt * 128 * 16; i += 256) {
            int tt = i / (128 * 16);
            int r  = i - tt * (128 * 16);
            int ci = r >> 4, q4 = r & 15;
            ((float4*)w_s)[tt * 128 * 16 + ci * 16 + q4] =
                ((const float4*)(g_w2t + ci * 576 + (2 * p + tt) * 64))[q4];
        }
        __syncthreads();

        u64 acc2[32];
#pragma unroll
        for (int i = 0; i < 32; ++i) acc2[i] = 0ull;

        for (int tt = 0; tt < nt; ++tt) {
            int t = 2 * p + tt;
            const float* wbase = w_s + tt * 8192;
            for (int ci = 0; ci < 128; ++ci) {
                const float* xrow = in_s + ci * 264 + t + l;
                u64 xd[8];
#pragma unroll
                for (int u = 0; u < 8; ++u) {
                    float xv = xrow[u * 32];
                    PACK2(xd[u], xv, xv);
                }
                const u64* wp = (const u64*)(wbase + ci * 64 + cobase);
                u64 w0 = wp[0], w1r = wp[1], w2r = wp[2], w3r = wp[3];
#pragma unroll
                for (int u = 0; u < 8; ++u) FMA2(acc2[0 * 8 + u], xd[u], w0);
#pragma unroll
                for (int u = 0; u < 8; ++u) FMA2(acc2[1 * 8 + u], xd[u], w1r);
#pragma unroll
                for (int u = 0; u < 8; ++u) FMA2(acc2[2 * 8 + u], xd[u], w2r);
#pragma unroll
                for (int u = 0; u < 8; ++u) FMA2(acc2[3 * 8 + u], xd[u], w3r);
            }
        }
#pragma unroll
        for (int i = 0; i < 32; ++i) ADD2(tot2[i], tot2[i], acc2[i]);
    }
    __syncthreads();

    // ---- epilogue: pool(3,3) + bias + relu ----
    float* conv_s = sm;  // 64 x 248 (aliases in_s, done with it)
#pragma unroll
    for (int cp = 0; cp < 4; ++cp)
#pragma unroll
        for (int u = 0; u < 8; ++u) {
            float lo, hi;
            UNPACK2(lo, hi, tot2[cp * 8 + u]);
            int j = u * 32 + l;
            if (j < 244) {
                conv_s[(cobase + 2 * cp + 0) * 248 + j] = lo;
                conv_s[(cobase + 2 * cp + 1) * 248 + j] = hi;
            }
        }
    __syncthreads();
    for (int idx = tid; idx < C2 * L2; idx += 256) {
        int co = idx / L2, i = idx - co * L2;
        const float* p3 = conv_s + co * 248 + 3 * i;
        float m = fmaxf(fmaxf(p3[0], p3[1]), p3[2]);
        g_buf2[(size_t)n * (C2 * L2) + idx] = fmaxf(__fadd_rn(m, b2[co]), 0.f);
    }
}

// ---------------------------------------------------------------------------
// k3: conv3 (f32x2 co-pair packed, K=192 chain t outer / ci inner) + pool +
// bias + relu, fc1 (10 parallel kc=256 panel chains), fc2 (+tanh), theta@B.
// ---------------------------------------------------------------------------
#define K3_INSTRIDE 100
#define K3_SMEM_FLOATS (64 * K3_INSTRIDE + 64 * 3 * 64)   // 18688
#define K3_SMEM_BYTES  (K3_SMEM_FLOATS * 4)               // 74752

__global__ __launch_bounds__(256, 2) void k3_tail(const float* __restrict__ b3,
                                                  const float* __restrict__ fb1,
                                                  const float* __restrict__ fw2,
                                                  const float* __restrict__ fb2,
                                                  const float* __restrict__ Bb) {
    extern __shared__ float sm[];
    float* in_s = sm;           // 64 * 100
    float* w_s  = sm + 6400;    // 12288

    int n   = blockIdx.x;
    int tid = threadIdx.x;
    int l   = tid & 31;
    int wg  = tid >> 5;
    int cobase = wg * 8;

    const float* inb = g_buf2 + (size_t)n * (C2 * L2);
    for (int idx = tid; idx < 64 * K3_INSTRIDE; idx += 256) {
        int ci = idx / K3_INSTRIDE, j = idx - ci * K3_INSTRIDE;
        in_s[idx] = (j < L2) ? inb[ci * L2 + j] : 0.f;
    }
    for (int idx = tid; idx < 64 * 3 * 64; idx += 256) w_s[idx] = g_w3t[idx];
    __syncthreads();

    u64 acc2[12];
#pragma unroll
    for (int i = 0; i < 12; ++i) acc2[i] = 0ull;

    for (int t = 0; t < 3; ++t) {
        for (int ci = 0; ci < 64; ++ci) {
            const float* xrow = in_s + ci * K3_INSTRIDE + t + l;
            u64 xd[3];
#pragma unroll
            for (int u = 0; u < 3; ++u) {
                float xv = xrow[u * 32];
                PACK2(xd[u], xv, xv);
            }
            const u64* wp = (const u64*)(w_s + ci * 192 + t * 64 + cobase);
            u64 w0 = wp[0], w1r = wp[1], w2r = wp[2], w3r = wp[3];
#pragma unroll
            for (int u = 0; u < 3; ++u) FMA2(acc2[0 * 3 + u], xd[u], w0);
#pragma unroll
            for (int u = 0; u < 3; ++u) FMA2(acc2[1 * 3 + u], xd[u], w1r);
#pragma unroll
            for (int u = 0; u < 3; ++u) FMA2(acc2[2 * 3 + u], xd[u], w2r);
#pragma unroll
            for (int u = 0; u < 3; ++u) FMA2(acc2[3 * 3 + u], xd[u], w3r);
        }
    }
    __syncthreads();

    float* conv_s = sm;  // 64 * 80
#pragma unroll
    for (int cp = 0; cp < 4; ++cp)
#pragma unroll
        for (int u = 0; u < 3; ++u) {
            float lo, hi;
            UNPACK2(lo, hi, acc2[cp * 3 + u]);
            int j = u * 32 + l;
            if (j < 80) {
                conv_s[(cobase + 2 * cp + 0) * 80 + j] = lo;
                conv_s[(cobase + 2 * cp + 1) * 80 + j] = hi;
            }
        }
    __syncthreads();

    float* xs_s = sm + 6400;
    for (int idx = tid; idx < C3 * L3; idx += 256) {
        int co = idx / L3, i = idx - co * L3;
        const float* p3 = conv_s + co * 80 + 2 * i;
        float m = fmaxf(fmaxf(p3[0], p3[1]), p3[2]);
        xs_s[idx] = fmaxf(__fadd_rn(m, b3[co]), 0.f);
    }
    __syncthreads();

    float* pan_s = xs_s + 2496;   // 160
    float* h_s   = pan_s + 160;   // 16
    float* th_s  = h_s + 16;      // 5

    if (tid < 160) {
        int o = tid & 15;
        int p = tid >> 4;
        int e0  = p * 256;
        int len = (p < 9) ? 256 : 192;
        float a = 0.f;
        const float* wt = g_fw1t + e0 * 16 + o;
#pragma unroll 8
        for (int q = 0; q < len; ++q)
            a = fmaf(xs_s[e0 + q], __ldg(wt + q * 16), a);
        pan_s[p * 16 + o] = a;
    }
    __syncthreads();

    if (tid < 16) {
        float tot = 0.f;
#pragma unroll
        for (int p = 0; p < 10; ++p)
            tot = __fadd_rn(tot, pan_s[p * 16 + tid]);
        h_s[tid] = fmaxf(__fadd_rn(tot, fb1[tid]), 0.f);
    }
    __syncthreads();

    if (tid < 5) {
        float z = 0.f;
#pragma unroll
        for (int m = 0; m < 16; ++m)
            z = __fadd_rn(z, __fmul_rn(h_s[m], fw2[tid * 16 + m]));
        z = __fadd_rn(z, fb2[tid]);
        th_s[tid] = tanh_xla(z);
    }
    __syncthreads();

    if (tid < 12) {
        float ab = 0.f;
#pragma unroll
        for (int m = 0; m < 5; ++m)
            ab = __fadd_rn(ab, __fmul_rn(th_s[m], Bb[tid * 5 + m]));
        g_ab[n * 12 + tid] = ab;
    }
}

// ---------------------------------------------------------------------------
// k4: CPAB integration (unchanged — bit-exact path)
// ---------------------------------------------------------------------------
__global__ __launch_bounds__(512) void k4_warp_interp(const float* __restrict__ xd,
                                                      float* __restrict__ out) {
    __shared__ float xs[L0];
    __shared__ float e_s[6], s_s[6];
    int n   = blockIdx.x;
    int tid = threadIdx.x;

    xs[tid] = xd[(size_t)n * L0 + tid];
    if (tid < 6) {
        float a = g_ab[n * 12 + 2 * tid];
        float b = g_ab[n * 12 + 2 * tid + 1];
        const float dtf = 0.02f;
        if (fabsf(a) < 1e-6f) {
            e_s[tid] = 1.0f;
            s_s[tid] = __fmul_rn(b, dtf);
        } else {
            float arg = __fmul_rn(a, dtf);
            float e   = cephes_expf(arg);
            e_s[tid] = e;
            float t2 = __fdiv_rn(b, a);
            float t3 = __fsub_rn(e, 1.0f);
            s_s[tid] = __fmul_rn(t2, t3);
        }
    }
    __syncthreads();

    const float stepf = 1.0f / 511.0f;
    float x = (tid == 511) ? 1.0f : __fmul_rn((float)tid, stepf);

#pragma unroll 1
    for (int s = 0; s < 50; ++s) {
        int c = (int)__fmul_rn(x, 6.0f);
        c = min(max(c, 0), 5);
        float xn = __fadd_rn(__fmul_rn(e_s[c], x), s_s[c]);
        x = fminf(fmaxf(xn, 0.0f), 1.0f);
    }

    float pos = __fmul_rn(x, 511.0f);
    int i0 = (int)floorf(pos);
    i0 = min(max(i0, 0), 510);
    float w  = __fsub_rn(pos, (float)i0);
    float g0 = xs[i0];
    float g1 = xs[i0 + 1];
    out[(size_t)n * L0 + tid] =
        __fadd_rn(__fmul_rn(g0, __fsub_rn(1.0f, w)), __fmul_rn(g1, w));
}

// ---------------------------------------------------------------------------
extern "C" void kernel_launch(void* const* d_in, const int* in_sizes, int n_in,
                              void* d_out, int out_size) {
    const float* x   = (const float*)d_in[0];
    const float* w1  = (const float*)d_in[1];
    const float* b1  = (const float*)d_in[2];
    const float* w2  = (const float*)d_in[3];
    const float* b2  = (const float*)d_in[4];
    const float* w3  = (const float*)d_in[5];
    const float* b3  = (const float*)d_in[6];
    const float* fw1 = (const float*)d_in[7];
    const float* fb1 = (const float*)d_in[8];
    const float* fw2 = (const float*)d_in[9];
    const float* fb2 = (const float*)d_in[10];
    const float* Bb  = (const float*)d_in[11];

    cudaFuncSetAttribute(k2_fused, cudaFuncAttributeMaxDynamicSharedMemorySize,
                         K2_SMEM_BYTES);
    cudaFuncSetAttribute(k3_tail, cudaFuncAttributeMaxDynamicSharedMemorySize,
                         K3_SMEM_BYTES);

    // 288 blocks x 256 = 73728 threads: covers g_w2t (128*9*64) exactly.
    k0_transpose<<<288, 256>>>(w2, w3, fw1);
    k2_fused<<<NSAMP, 256, K2_SMEM_BYTES>>>(x, w1, b1, b2);
    k3_tail<<<NSAMP, 256, K3_SMEM_BYTES>>>(b3, fb1, fw2, fb2, Bb);
    k4_warp_interp<<<NSAMP, 512>>>(x, (float*)d_out);
}